// round 2
// baseline (speedup 1.0000x reference)
#include <cuda_runtime.h>
#include <math.h>

#define Bsz 4
#define S 1024
#define D 512
#define H 8
#define DH 64
#define NBH (Bsz*H)
#define SCALE 0.125f   // DH^-0.5 = 1/8

// ---------------- scratch (device globals: allocation-guard safe) ----------
__device__ float g_Q[NBH * S * DH];   // [B,H,S,DH]
__device__ float g_K[NBH * S * DH];
__device__ float g_V[NBH * S * DH];
__device__ float g_P[(size_t)NBH * S * S];  // logits -> weights (128 MB)
__device__ float g_C[Bsz * S * D];    // ctx in [B,S,D] layout

// ============================================================================
// K1: fused QKV projection.  z in {0,1,2} selects (X, W, dst).
// C[4096,512] = X[4096,512] @ W[512,512], scattered to [B,H,S,DH] layout.
// Tile 64x64, BK=16, 256 threads, 4x4 per thread.
// ============================================================================
__global__ void proj_kernel(const float* __restrict__ Xq,
                            const float* __restrict__ Xk,
                            const float* __restrict__ Xv,
                            const float* __restrict__ Wq,
                            const float* __restrict__ Wk,
                            const float* __restrict__ Wv) {
    const int BM = 64, BN = 64, BK = 16;
    int which = blockIdx.z;
    const float* X = (which == 0) ? Xq : (which == 1) ? Xk : Xv;
    const float* W = (which == 0) ? Wq : (which == 1) ? Wk : Wv;
    float* O = (which == 0) ? g_Q : (which == 1) ? g_K : g_V;

    __shared__ float As[BK][BM];
    __shared__ float Bs[BK][BN];

    int tid = threadIdx.x;
    int tx = tid & 15, ty = tid >> 4;
    int m0 = blockIdx.y * BM;
    int n0 = blockIdx.x * BN;

    float acc[4][4] = {};

    for (int k0 = 0; k0 < D; k0 += BK) {
        {   // load A tile (transposed into As[k][m])
            int m = tid >> 2, k4 = (tid & 3) * 4;
            float4 a = *(const float4*)(X + (size_t)(m0 + m) * D + k0 + k4);
            As[k4 + 0][m] = a.x; As[k4 + 1][m] = a.y;
            As[k4 + 2][m] = a.z; As[k4 + 3][m] = a.w;
        }
        {   // load B tile
            int k = tid >> 4, n4 = (tid & 15) * 4;
            *(float4*)&Bs[k][n4] = *(const float4*)(W + (size_t)(k0 + k) * D + n0 + n4);
        }
        __syncthreads();
        #pragma unroll
        for (int kk = 0; kk < BK; kk++) {
            float a[4], b[4];
            #pragma unroll
            for (int i = 0; i < 4; i++) a[i] = As[kk][ty * 4 + i];
            #pragma unroll
            for (int j = 0; j < 4; j++) b[j] = Bs[kk][tx * 4 + j];
            #pragma unroll
            for (int i = 0; i < 4; i++)
                #pragma unroll
                for (int j = 0; j < 4; j++)
                    acc[i][j] += a[i] * b[j];
        }
        __syncthreads();
    }

    #pragma unroll
    for (int i = 0; i < 4; i++) {
        int row = m0 + ty * 4 + i;
        int b = row / S, s = row - b * S;
        #pragma unroll
        for (int j = 0; j < 4; j++) {
            int col = n0 + tx * 4 + j;
            int h = col / DH, d = col - h * DH;
            O[(((size_t)(b * H + h)) * S + s) * DH + d] = acc[i][j];
        }
    }
}

// ============================================================================
// K2: logits[b,h,s,t] = scale * ( q_s·k_t + q_s·rel[h,:,S-1-s+t] )  for t<=s
//                       -1e30                                       for t>s
// The rel term is the algebraic reduction of the mask+pad+reshape skew trick.
// Per tile, rel columns needed span a window of BM+BN-1 = 127 columns.
// ============================================================================
__global__ void logits_kernel(const float* __restrict__ rel) {
    const int BM = 64, BN = 64, BK = 16;
    int bh = blockIdx.z;
    int h = bh % H;
    int s0 = blockIdx.y * BM;
    int t0 = blockIdx.x * BN;
    float* P = g_P + (size_t)bh * S * S;
    int tid = threadIdx.x;

    if (t0 >= s0 + BM) {  // tile fully above diagonal -> masked
        for (int e = tid; e < BM * BN / 4; e += 256) {
            int m = e >> 4, n4 = (e & 15) * 4;
            float4 v = make_float4(-1e30f, -1e30f, -1e30f, -1e30f);
            *(float4*)&P[(size_t)(s0 + m) * S + t0 + n4] = v;
        }
        return;
    }

    const float* Q = g_Q + (size_t)bh * S * DH;
    const float* K = g_K + (size_t)bh * S * DH;

    __shared__ float Qs[BK][BM];
    __shared__ float Ks[BK][BN];
    __shared__ float Rs[BK][BM + BN];  // 127 used, 128 padded

    int tx = tid & 15, ty = tid >> 4;
    int lbase = t0 - s0 + (S - BM);  // l = lbase + w, w = (t-t0)-(s-s0)+BM-1

    float acc[4][4] = {};

    for (int k0 = 0; k0 < DH; k0 += BK) {
        {   // Q tile transposed
            int m = tid >> 2, k4 = (tid & 3) * 4;
            float4 a = *(const float4*)(Q + (size_t)(s0 + m) * DH + k0 + k4);
            Qs[k4 + 0][m] = a.x; Qs[k4 + 1][m] = a.y;
            Qs[k4 + 2][m] = a.z; Qs[k4 + 3][m] = a.w;
        }
        {   // K tile transposed
            int m = tid >> 2, k4 = (tid & 3) * 4;
            float4 a = *(const float4*)(K + (size_t)(t0 + m) * DH + k0 + k4);
            Ks[k4 + 0][m] = a.x; Ks[k4 + 1][m] = a.y;
            Ks[k4 + 2][m] = a.z; Ks[k4 + 3][m] = a.w;
        }
        // rel window: Rs[kk][w] = rel[h, k0+kk, lbase+w] (0 if OOB)
        for (int e = tid; e < BK * 128; e += 256) {
            int kk = e >> 7, w = e & 127;
            int l = lbase + w;
            int d = k0 + kk;
            Rs[kk][w] = (l >= 0 && l < S)
                            ? rel[((size_t)h * DH + d) * S + l] : 0.0f;
        }
        __syncthreads();
        #pragma unroll
        for (int kk = 0; kk < BK; kk++) {
            float a[4], b[4];
            #pragma unroll
            for (int i = 0; i < 4; i++) a[i] = Qs[kk][ty * 4 + i];
            #pragma unroll
            for (int j = 0; j < 4; j++) b[j] = Ks[kk][tx * 4 + j];
            #pragma unroll
            for (int i = 0; i < 4; i++) {
                #pragma unroll
                for (int j = 0; j < 4; j++) {
                    int w = (tx * 4 + j) - (ty * 4 + i) + (BM - 1);
                    acc[i][j] += a[i] * (b[j] + Rs[kk][w]);
                }
            }
        }
        __syncthreads();
    }

    #pragma unroll
    for (int i = 0; i < 4; i++) {
        int s = s0 + ty * 4 + i;
        #pragma unroll
        for (int j = 0; j < 4; j++) {
            int t = t0 + tx * 4 + j;
            P[(size_t)s * S + t] = (t <= s) ? acc[i][j] * SCALE : -1e30f;
        }
    }
}

// ============================================================================
// K3: row softmax over g_P (in place).  One block per row of 1024.
// ============================================================================
__global__ void softmax_kernel() {
    size_t row = blockIdx.x;
    float* p = g_P + row * (size_t)S;
    int tid = threadIdx.x;  // 256
    float4 v = reinterpret_cast<float4*>(p)[tid];

    __shared__ float smax[8];
    __shared__ float ssum[8];

    float m = fmaxf(fmaxf(v.x, v.y), fmaxf(v.z, v.w));
    #pragma unroll
    for (int o = 16; o > 0; o >>= 1) m = fmaxf(m, __shfl_xor_sync(0xffffffffu, m, o));
    if ((tid & 31) == 0) smax[tid >> 5] = m;
    __syncthreads();
    float rm = smax[0];
    #pragma unroll
    for (int i = 1; i < 8; i++) rm = fmaxf(rm, smax[i]);

    float e0 = __expf(v.x - rm), e1 = __expf(v.y - rm);
    float e2 = __expf(v.z - rm), e3 = __expf(v.w - rm);
    float sum = e0 + e1 + e2 + e3;
    #pragma unroll
    for (int o = 16; o > 0; o >>= 1) sum += __shfl_xor_sync(0xffffffffu, sum, o);
    if ((tid & 31) == 0) ssum[tid >> 5] = sum;
    __syncthreads();
    float rs = 0.0f;
    #pragma unroll
    for (int i = 0; i < 8; i++) rs += ssum[i];
    float inv = 1.0f / rs;

    v = make_float4(e0 * inv, e1 * inv, e2 * inv, e3 * inv);
    reinterpret_cast<float4*>(p)[tid] = v;
}

// ============================================================================
// K4: ctx[b,s,h*DH+d] = sum_t weights[b,h,s,t] * v[b,h,t,d]
// Causality: weights[s,t]=0 for t>s, so K-loop truncates at s0+BM.
// ============================================================================
__global__ void ctx_kernel() {
    const int BM = 64, BN = 64, BK = 16;  // BN == DH
    int bh = blockIdx.z;
    int b = bh / H, h = bh % H;
    int s0 = blockIdx.y * BM;

    const float* Wt = g_P + (size_t)bh * S * S;
    const float* V  = g_V + (size_t)bh * S * DH;

    __shared__ float As[BK][BM];
    __shared__ float Bs[BK][BN];

    int tid = threadIdx.x;
    int tx = tid & 15, ty = tid >> 4;
    float acc[4][4] = {};

    int kend = s0 + BM;  // exclusive; weights beyond are exactly 0

    for (int k0 = 0; k0 < kend; k0 += BK) {
        {
            int m = tid >> 2, k4 = (tid & 3) * 4;
            float4 a = *(const float4*)(Wt + (size_t)(s0 + m) * S + k0 + k4);
            As[k4 + 0][m] = a.x; As[k4 + 1][m] = a.y;
            As[k4 + 2][m] = a.z; As[k4 + 3][m] = a.w;
        }
        {
            int k = tid >> 4, n4 = (tid & 15) * 4;
            *(float4*)&Bs[k][n4] = *(const float4*)(V + (size_t)(k0 + k) * DH + n4);
        }
        __syncthreads();
        #pragma unroll
        for (int kk = 0; kk < BK; kk++) {
            float a[4], bb[4];
            #pragma unroll
            for (int i = 0; i < 4; i++) a[i] = As[kk][ty * 4 + i];
            #pragma unroll
            for (int j = 0; j < 4; j++) bb[j] = Bs[kk][tx * 4 + j];
            #pragma unroll
            for (int i = 0; i < 4; i++)
                #pragma unroll
                for (int j = 0; j < 4; j++)
                    acc[i][j] += a[i] * bb[j];
        }
        __syncthreads();
    }

    #pragma unroll
    for (int i = 0; i < 4; i++) {
        int s = s0 + ty * 4 + i;
        #pragma unroll
        for (int j = 0; j < 4; j++) {
            int d = tx * 4 + j;
            g_C[((size_t)(b * S + s)) * D + h * DH + d] = acc[i][j];
        }
    }
}

// ============================================================================
// K5: out[4096,512] = ctx[4096,512] @ Wo[512,512]
// ============================================================================
__global__ void out_kernel(const float* __restrict__ Wo, float* __restrict__ out) {
    const int BM = 64, BN = 64, BK = 16;
    __shared__ float As[BK][BM];
    __shared__ float Bs[BK][BN];

    int tid = threadIdx.x;
    int tx = tid & 15, ty = tid >> 4;
    int m0 = blockIdx.y * BM;
    int n0 = blockIdx.x * BN;
    float acc[4][4] = {};

    for (int k0 = 0; k0 < D; k0 += BK) {
        {
            int m = tid >> 2, k4 = (tid & 3) * 4;
            float4 a = *(const float4*)(g_C + (size_t)(m0 + m) * D + k0 + k4);
            As[k4 + 0][m] = a.x; As[k4 + 1][m] = a.y;
            As[k4 + 2][m] = a.z; As[k4 + 3][m] = a.w;
        }
        {
            int k = tid >> 4, n4 = (tid & 15) * 4;
            *(float4*)&Bs[k][n4] = *(const float4*)(Wo + (size_t)(k0 + k) * D + n0 + n4);
        }
        __syncthreads();
        #pragma unroll
        for (int kk = 0; kk < BK; kk++) {
            float a[4], b[4];
            #pragma unroll
            for (int i = 0; i < 4; i++) a[i] = As[kk][ty * 4 + i];
            #pragma unroll
            for (int j = 0; j < 4; j++) b[j] = Bs[kk][tx * 4 + j];
            #pragma unroll
            for (int i = 0; i < 4; i++)
                #pragma unroll
                for (int j = 0; j < 4; j++)
                    acc[i][j] += a[i] * b[j];
        }
        __syncthreads();
    }

    #pragma unroll
    for (int i = 0; i < 4; i++) {
        int row = m0 + ty * 4 + i;
        #pragma unroll
        for (int j = 0; j < 4; j++) {
            int col = n0 + tx * 4 + j;
            out[(size_t)row * D + col] = acc[i][j];
        }
    }
}

// ============================================================================
extern "C" void kernel_launch(void* const* d_in, const int* in_sizes, int n_in,
                              void* d_out, int out_size) {
    const float* queries = (const float*)d_in[0];
    const float* keys    = (const float*)d_in[1];
    const float* values  = (const float*)d_in[2];
    // d_in[3] = mask: causal, reproduced analytically
    const float* Wq      = (const float*)d_in[4];
    const float* Wk      = (const float*)d_in[5];
    const float* Wv      = (const float*)d_in[6];
    const float* Wo      = (const float*)d_in[7];
    const float* rel     = (const float*)d_in[8];
    float* out = (float*)d_out;

    proj_kernel<<<dim3(D / 64, (Bsz * S) / 64, 3), 256>>>(queries, keys, values, Wq, Wk, Wv);
    logits_kernel<<<dim3(S / 64, S / 64, NBH), 256>>>(rel);
    softmax_kernel<<<NBH * S, 256>>>();
    ctx_kernel<<<dim3(1, S / 64, NBH), 256>>>();
    out_kernel<<<dim3(D / 64, (Bsz * S) / 64, 1), 256>>>(Wo, out);
}

// round 3
// speedup vs baseline: 1.4616x; 1.4616x over previous
#include <cuda_runtime.h>
#include <math.h>

#define Bsz 4
#define S 1024
#define D 512
#define H 8
#define DH 64
#define NBH (Bsz*H)
#define SCALE 0.125f   // DH^-0.5 = 1/8

// ---------------- scratch (device globals: allocation-guard safe) ----------
__device__ float g_Q[NBH * S * DH];   // [B,H,S,DH]
__device__ float g_K[NBH * S * DH];
__device__ float g_V[NBH * S * DH];
__device__ float g_C[Bsz * S * D];    // ctx in [B,S,D] layout

// ============================================================================
// K1: fused QKV projection.  z in {0,1,2} selects (X, W, dst).
// C[4096,512] = X[4096,512] @ W[512,512], scattered to [B,H,S,DH] layout.
// ============================================================================
__global__ void proj_kernel(const float* __restrict__ Xq,
                            const float* __restrict__ Xk,
                            const float* __restrict__ Xv,
                            const float* __restrict__ Wq,
                            const float* __restrict__ Wk,
                            const float* __restrict__ Wv) {
    const int BM = 64, BN = 64, BK = 16;
    int which = blockIdx.z;
    const float* X = (which == 0) ? Xq : (which == 1) ? Xk : Xv;
    const float* W = (which == 0) ? Wq : (which == 1) ? Wk : Wv;
    float* O = (which == 0) ? g_Q : (which == 1) ? g_K : g_V;

    __shared__ float As[BK][BM];
    __shared__ float Bs[BK][BN];

    int tid = threadIdx.x;
    int tx = tid & 15, ty = tid >> 4;
    int m0 = blockIdx.y * BM;
    int n0 = blockIdx.x * BN;

    float acc[4][4] = {};

    for (int k0 = 0; k0 < D; k0 += BK) {
        {   // load A tile (transposed into As[k][m])
            int m = tid >> 2, k4 = (tid & 3) * 4;
            float4 a = *(const float4*)(X + (size_t)(m0 + m) * D + k0 + k4);
            As[k4 + 0][m] = a.x; As[k4 + 1][m] = a.y;
            As[k4 + 2][m] = a.z; As[k4 + 3][m] = a.w;
        }
        {   // load B tile
            int k = tid >> 4, n4 = (tid & 15) * 4;
            *(float4*)&Bs[k][n4] = *(const float4*)(W + (size_t)(k0 + k) * D + n0 + n4);
        }
        __syncthreads();
        #pragma unroll
        for (int kk = 0; kk < BK; kk++) {
            float a[4], b[4];
            #pragma unroll
            for (int i = 0; i < 4; i++) a[i] = As[kk][ty * 4 + i];
            #pragma unroll
            for (int j = 0; j < 4; j++) b[j] = Bs[kk][tx * 4 + j];
            #pragma unroll
            for (int i = 0; i < 4; i++)
                #pragma unroll
                for (int j = 0; j < 4; j++)
                    acc[i][j] += a[i] * b[j];
        }
        __syncthreads();
    }

    #pragma unroll
    for (int i = 0; i < 4; i++) {
        int row = m0 + ty * 4 + i;
        int b = row / S, s = row - b * S;
        #pragma unroll
        for (int j = 0; j < 4; j++) {
            int col = n0 + tx * 4 + j;
            int h = col / DH, d = col - h * DH;
            O[(((size_t)(b * H + h)) * S + s) * DH + d] = acc[i][j];
        }
    }
}

// ============================================================================
// K2: fused flash attention (causal + skewed rel bias), fp32.
// Per block: one (bh, 64-row s-tile). Online softmax across t-tiles of 64.
//   logits[s,t] = SCALE*( q_s·k_t + q_s·rel[h,:,1023-s+t] )  for t<=s
// Per thread: 4x4 of the 64x64 logits tile and 4x4 of the 64-wide O tile.
// The rel lookup collapses to 7 diagonals per thread -> two float4 LDS.
// Block order: heaviest s-tiles first (LPT) for load balance.
// ============================================================================
__global__ void __launch_bounds__(256) flash_kernel(const float* __restrict__ rel) {
    int idx = blockIdx.x;
    int s_tile = 15 - (idx >> 5);     // 15..0: heavy blocks launched first
    int bh = idx & 31;
    int h = bh & 7;
    int b = bh >> 3;
    int s0 = s_tile * 64;

    const float* Q = g_Q + (size_t)bh * S * DH;
    const float* K = g_K + (size_t)bh * S * DH;
    const float* V = g_V + (size_t)bh * S * DH;

    __shared__ float Qs[64 * 64];     // Qs[k][s]  (transposed)
    __shared__ float Ps[64 * 64];     // P[s][t]
    __shared__ float Ks[16 * 64];     // K chunk, Ks[k][t] (transposed)
    __shared__ float RsVs[16 * 128];  // Rs[16][128] in QK phase / Vs[16][64] in PV

    int tid = threadIdx.x;
    int tx = tid & 15, ty = tid >> 4;

    // ---- load Q tile once, transposed ----
    {
        int m = tid >> 2, kq = (tid & 3) * 4;
        const float* qp = Q + (size_t)(s0 + m) * DH;
        #pragma unroll
        for (int pass = 0; pass < 4; pass++) {
            int k4 = kq + pass * 16;
            float4 a = *(const float4*)(qp + k4);
            Qs[(k4 + 0) * 64 + m] = a.x;
            Qs[(k4 + 1) * 64 + m] = a.y;
            Qs[(k4 + 2) * 64 + m] = a.z;
            Qs[(k4 + 3) * 64 + m] = a.w;
        }
    }

    float O[4][4] = {};
    float mrow[4] = {-1e30f, -1e30f, -1e30f, -1e30f};
    float lrow[4] = {};

    const int wbase = 4 * (tx - ty) + 60;   // rel-diagonal window base, in [0,120]

    for (int it = 0; it <= s_tile; it++) {
        int t0 = it * 64;
        int lbase = t0 - s0 + 960;          // l = lbase + w
        float acc[4][4] = {};

        // ---------- QK + rel, in 4 chunks of k ----------
        #pragma unroll
        for (int c = 0; c < 4; c++) {
            int k0 = c * 16;
            {   // K chunk transposed
                int t = tid >> 2, kq = (tid & 3) * 4;
                float4 kv = *(const float4*)(K + (size_t)(t0 + t) * DH + k0 + kq);
                Ks[(kq + 0) * 64 + t] = kv.x;
                Ks[(kq + 1) * 64 + t] = kv.y;
                Ks[(kq + 2) * 64 + t] = kv.z;
                Ks[(kq + 3) * 64 + t] = kv.w;
            }
            {   // rel window chunk: Rs[kl][w] = rel[h, k0+kl, lbase+w] (0 if OOB)
                #pragma unroll
                for (int r = 0; r < 2; r++) {
                    int e = tid + r * 256;          // 0..511 float4 slots
                    int kl = e >> 5;
                    int w4 = (e & 31) * 4;
                    int l = lbase + w4;             // lbase >= 0 always; check upper
                    float4 v;
                    if (l < S)
                        v = *(const float4*)(rel + (size_t)(h * DH + k0 + kl) * S + l);
                    else
                        v = make_float4(0.f, 0.f, 0.f, 0.f);
                    *(float4*)&RsVs[kl * 128 + w4] = v;
                }
            }
            __syncthreads();
            #pragma unroll
            for (int kl = 0; kl < 16; kl++) {
                float4 av = *(const float4*)&Qs[(k0 + kl) * 64 + ty * 4];
                float4 bv = *(const float4*)&Ks[kl * 64 + tx * 4];
                float4 r0 = *(const float4*)&RsVs[kl * 128 + wbase];
                float4 r1 = *(const float4*)&RsVs[kl * 128 + wbase + 4];
                float a[4] = {av.x, av.y, av.z, av.w};
                float bb[4] = {bv.x, bv.y, bv.z, bv.w};
                float rr[8] = {r0.x, r0.y, r0.z, r0.w, r1.x, r1.y, r1.z, r1.w};
                #pragma unroll
                for (int i = 0; i < 4; i++)
                    #pragma unroll
                    for (int j = 0; j < 4; j++)
                        acc[i][j] += a[i] * (bb[j] + rr[j - i + 3]);
            }
            __syncthreads();
        }

        // ---------- mask (diagonal tile only) + scale ----------
        bool diag = (it == s_tile);
        #pragma unroll
        for (int i = 0; i < 4; i++)
            #pragma unroll
            for (int j = 0; j < 4; j++) {
                float vsc = acc[i][j] * SCALE;
                if (diag && (tx * 4 + j > ty * 4 + i)) vsc = -1e30f;
                acc[i][j] = vsc;
            }

        // ---------- online softmax update (rows owned by 16 tx lanes) ----------
        #pragma unroll
        for (int i = 0; i < 4; i++) {
            float mx = fmaxf(fmaxf(acc[i][0], acc[i][1]), fmaxf(acc[i][2], acc[i][3]));
            #pragma unroll
            for (int o = 8; o > 0; o >>= 1)
                mx = fmaxf(mx, __shfl_xor_sync(0xffffffffu, mx, o));
            float mnew = fmaxf(mrow[i], mx);
            float alpha = __expf(mrow[i] - mnew);
            mrow[i] = mnew;
            float rs = 0.f;
            #pragma unroll
            for (int j = 0; j < 4; j++) {
                float p = __expf(acc[i][j] - mnew);
                acc[i][j] = p;
                rs += p;
            }
            #pragma unroll
            for (int o = 8; o > 0; o >>= 1)
                rs += __shfl_xor_sync(0xffffffffu, rs, o);
            lrow[i] = lrow[i] * alpha + rs;
            #pragma unroll
            for (int j = 0; j < 4; j++) O[i][j] *= alpha;
        }

        // ---------- stage P ----------
        #pragma unroll
        for (int i = 0; i < 4; i++) {
            float4 pv = make_float4(acc[i][0], acc[i][1], acc[i][2], acc[i][3]);
            *(float4*)&Ps[(ty * 4 + i) * 64 + tx * 4] = pv;
        }
        __syncthreads();

        // ---------- PV, in 4 chunks of t ----------
        #pragma unroll
        for (int c = 0; c < 4; c++) {
            int tc0 = c * 16;
            {   // V chunk natural layout: Vs[kl][d]
                int k = tid >> 4, n4 = (tid & 15) * 4;
                *(float4*)&RsVs[k * 64 + n4] =
                    *(const float4*)(V + (size_t)(t0 + tc0 + k) * DH + n4);
            }
            __syncthreads();
            #pragma unroll
            for (int kl = 0; kl < 16; kl++) {
                float aP[4];
                #pragma unroll
                for (int i = 0; i < 4; i++)
                    aP[i] = Ps[(ty * 4 + i) * 64 + tc0 + kl];
                float4 bv = *(const float4*)&RsVs[kl * 64 + tx * 4];
                float bb[4] = {bv.x, bv.y, bv.z, bv.w};
                #pragma unroll
                for (int i = 0; i < 4; i++)
                    #pragma unroll
                    for (int j = 0; j < 4; j++)
                        O[i][j] += aP[i] * bb[j];
            }
            __syncthreads();
        }
    }

    // ---------- normalize + write ctx in [B,S,D] ----------
    #pragma unroll
    for (int i = 0; i < 4; i++) {
        float inv = 1.0f / lrow[i];
        float4 ov = make_float4(O[i][0] * inv, O[i][1] * inv,
                                O[i][2] * inv, O[i][3] * inv);
        *(float4*)&g_C[((size_t)(b * S + s0 + ty * 4 + i)) * D + h * DH + tx * 4] = ov;
    }
}

// ============================================================================
// K3: out[4096,512] = ctx[4096,512] @ Wo[512,512]
// ============================================================================
__global__ void out_kernel(const float* __restrict__ Wo, float* __restrict__ out) {
    const int BM = 64, BN = 64, BK = 16;
    __shared__ float As[BK][BM];
    __shared__ float Bs[BK][BN];

    int tid = threadIdx.x;
    int tx = tid & 15, ty = tid >> 4;
    int m0 = blockIdx.y * BM;
    int n0 = blockIdx.x * BN;
    float acc[4][4] = {};

    for (int k0 = 0; k0 < D; k0 += BK) {
        {
            int m = tid >> 2, k4 = (tid & 3) * 4;
            float4 a = *(const float4*)(g_C + (size_t)(m0 + m) * D + k0 + k4);
            As[k4 + 0][m] = a.x; As[k4 + 1][m] = a.y;
            As[k4 + 2][m] = a.z; As[k4 + 3][m] = a.w;
        }
        {
            int k = tid >> 4, n4 = (tid & 15) * 4;
            *(float4*)&Bs[k][n4] = *(const float4*)(Wo + (size_t)(k0 + k) * D + n0 + n4);
        }
        __syncthreads();
        #pragma unroll
        for (int kk = 0; kk < BK; kk++) {
            float a[4], b[4];
            #pragma unroll
            for (int i = 0; i < 4; i++) a[i] = As[kk][ty * 4 + i];
            #pragma unroll
            for (int j = 0; j < 4; j++) b[j] = Bs[kk][tx * 4 + j];
            #pragma unroll
            for (int i = 0; i < 4; i++)
                #pragma unroll
                for (int j = 0; j < 4; j++)
                    acc[i][j] += a[i] * b[j];
        }
        __syncthreads();
    }

    #pragma unroll
    for (int i = 0; i < 4; i++) {
        int row = m0 + ty * 4 + i;
        #pragma unroll
        for (int j = 0; j < 4; j++) {
            int col = n0 + tx * 4 + j;
            out[(size_t)row * D + col] = acc[i][j];
        }
    }
}

// ============================================================================
extern "C" void kernel_launch(void* const* d_in, const int* in_sizes, int n_in,
                              void* d_out, int out_size) {
    const float* queries = (const float*)d_in[0];
    const float* keys    = (const float*)d_in[1];
    const float* values  = (const float*)d_in[2];
    // d_in[3] = mask: causal, reproduced analytically
    const float* Wq      = (const float*)d_in[4];
    const float* Wk      = (const float*)d_in[5];
    const float* Wv      = (const float*)d_in[6];
    const float* Wo      = (const float*)d_in[7];
    const float* rel     = (const float*)d_in[8];
    float* out = (float*)d_out;

    proj_kernel<<<dim3(D / 64, (Bsz * S) / 64, 3), 256>>>(queries, keys, values, Wq, Wk, Wv);
    flash_kernel<<<16 * NBH, 256>>>(rel);
    out_kernel<<<dim3(D / 64, (Bsz * S) / 64, 1), 256>>>(Wo, out);
}